// round 3
// baseline (speedup 1.0000x reference)
#include <cuda_runtime.h>
#include <cuda_bf16.h>
#include <cstdint>

// Sinkhorn, 32 x 1024 x 1024, tau=1, 10 iterations.
// Linear-domain rank-1 scaling:
//   E = exp(s); even iter: a_i = 1/sum_j E_ij b_j ; odd iter: b_j = 1/sum_i E_ij a_i
//   out = exp(s) * a_i * b_j
// E cached once in bf16 (64 MB, L2-resident); final pass recomputes exp in fp32.

#define BATCH 32
#define N 1024
#define RPB 128          // rows per block in the column pass
#define NCHUNK 8         // row chunks (N / RPB)

__device__ __nv_bfloat16 g_E[(size_t)BATCH * N * N];   // 64 MB scratch
__device__ float g_part[NCHUNK][BATCH][N];             // 1 MB partials
__device__ float g_a[BATCH * N];
__device__ float g_b[BATCH * N];

// ---------------------------------------------------------------------------
// K1: E = exp(s) -> bf16; a_i = 1/rowsum. Warp per row, 8 rows per block.
// grid (N/8, BATCH), 256 threads. Lane handles 32 floats (8x float4, MLP=8).
__global__ void k_exp_rowsum(const float* __restrict__ s) {
    const int w    = threadIdx.x >> 5;
    const int lane = threadIdx.x & 31;
    const int row  = blockIdx.x * 8 + w;
    const int b    = blockIdx.y;
    const size_t base = ((size_t)b * N + row) * N;

    float sum = 0.f;
    #pragma unroll
    for (int k = 0; k < 8; ++k) {
        const int j = (lane + 32 * k) * 4;
        float4 sv = *reinterpret_cast<const float4*>(s + base + j);
        float e0 = __expf(sv.x), e1 = __expf(sv.y);
        float e2 = __expf(sv.z), e3 = __expf(sv.w);
        __nv_bfloat162 p0 = __floats2bfloat162_rn(e0, e1);
        __nv_bfloat162 p1 = __floats2bfloat162_rn(e2, e3);
        uint2 packed;
        packed.x = *reinterpret_cast<uint32_t*>(&p0);
        packed.y = *reinterpret_cast<uint32_t*>(&p1);
        *reinterpret_cast<uint2*>(&g_E[base + j]) = packed;
        sum += (e0 + e1) + (e2 + e3);
    }
    #pragma unroll
    for (int o = 16; o > 0; o >>= 1) sum += __shfl_down_sync(0xFFFFFFFFu, sum, o);
    if (lane == 0) g_a[b * N + row] = 1.0f / sum;
}

// ---------------------------------------------------------------------------
// Row pass: a_i = 1/sum_j E_ij b_j. Warp per row, 8 rows per block.
// grid (N/8, BATCH), 256 threads. Lane: 4x (uint4 E + 2x float4 b).
__global__ void k_row() {
    const int w    = threadIdx.x >> 5;
    const int lane = threadIdx.x & 31;
    const int row  = blockIdx.x * 8 + w;
    const int b    = blockIdx.y;
    const size_t base = ((size_t)b * N + row) * N;
    const float* __restrict__ bp = &g_b[b * N];

    float sum = 0.f;
    #pragma unroll
    for (int k = 0; k < 4; ++k) {
        const int j = lane * 8 + 256 * k;
        uint4 u = *reinterpret_cast<const uint4*>(&g_E[base + j]);
        float4 bv0 = *reinterpret_cast<const float4*>(bp + j);
        float4 bv1 = *reinterpret_cast<const float4*>(bp + j + 4);
        float2 f0 = __bfloat1622float2(*reinterpret_cast<__nv_bfloat162*>(&u.x));
        float2 f1 = __bfloat1622float2(*reinterpret_cast<__nv_bfloat162*>(&u.y));
        float2 f2 = __bfloat1622float2(*reinterpret_cast<__nv_bfloat162*>(&u.z));
        float2 f3 = __bfloat1622float2(*reinterpret_cast<__nv_bfloat162*>(&u.w));
        sum = fmaf(f0.x, bv0.x, sum); sum = fmaf(f0.y, bv0.y, sum);
        sum = fmaf(f1.x, bv0.z, sum); sum = fmaf(f1.y, bv0.w, sum);
        sum = fmaf(f2.x, bv1.x, sum); sum = fmaf(f2.y, bv1.y, sum);
        sum = fmaf(f3.x, bv1.z, sum); sum = fmaf(f3.y, bv1.w, sum);
    }
    #pragma unroll
    for (int o = 16; o > 0; o >>= 1) sum += __shfl_down_sync(0xFFFFFFFFu, sum, o);
    if (lane == 0) g_a[b * N + row] = 1.0f / sum;
}

// ---------------------------------------------------------------------------
// Column pass stage 1: partial sums of E^T a over a 128-row chunk.
// grid (4 col-tiles, 8 row-chunks, 32 batch), 256 threads (8 warps).
// Lane owns 8 contiguous cols (uint4 = 16 B); warp covers a 512 B row segment.
// Warp w handles local rows w, w+8, ... (16 rows, unrolled 4 -> MLP 4x16B).
__global__ void k_col_partial() {
    __shared__ float sa[RPB];
    __shared__ float red[8][256];
    const int tile  = blockIdx.x;      // 0..3
    const int chunk = blockIdx.y;      // 0..7
    const int b     = blockIdx.z;      // 0..31
    const int w    = threadIdx.x >> 5;
    const int lane = threadIdx.x & 31;
    const int r0   = chunk * RPB;

    if (threadIdx.x < RPB / 4) {
        reinterpret_cast<float4*>(sa)[threadIdx.x] =
            reinterpret_cast<const float4*>(&g_a[b * N + r0])[threadIdx.x];
    }
    __syncthreads();

    const int col = tile * 256 + lane * 8;
    const size_t cbase = (size_t)b * N * N + col;

    float acc[8] = {0.f, 0.f, 0.f, 0.f, 0.f, 0.f, 0.f, 0.f};
    #pragma unroll 1
    for (int it = 0; it < 4; ++it) {
        uint4 u[4];
        float av[4];
        #pragma unroll
        for (int v = 0; v < 4; ++v) {
            const int rl = (it * 4 + v) * 8 + w;      // local row 0..127
            u[v]  = *reinterpret_cast<const uint4*>(&g_E[cbase + (size_t)(r0 + rl) * N]);
            av[v] = sa[rl];
        }
        #pragma unroll
        for (int v = 0; v < 4; ++v) {
            float2 f0 = __bfloat1622float2(*reinterpret_cast<__nv_bfloat162*>(&u[v].x));
            float2 f1 = __bfloat1622float2(*reinterpret_cast<__nv_bfloat162*>(&u[v].y));
            float2 f2 = __bfloat1622float2(*reinterpret_cast<__nv_bfloat162*>(&u[v].z));
            float2 f3 = __bfloat1622float2(*reinterpret_cast<__nv_bfloat162*>(&u[v].w));
            acc[0] = fmaf(av[v], f0.x, acc[0]);
            acc[1] = fmaf(av[v], f0.y, acc[1]);
            acc[2] = fmaf(av[v], f1.x, acc[2]);
            acc[3] = fmaf(av[v], f1.y, acc[3]);
            acc[4] = fmaf(av[v], f2.x, acc[4]);
            acc[5] = fmaf(av[v], f2.y, acc[5]);
            acc[6] = fmaf(av[v], f3.x, acc[6]);
            acc[7] = fmaf(av[v], f3.y, acc[7]);
        }
    }

    #pragma unroll
    for (int k = 0; k < 8; ++k) red[w][lane * 8 + k] = acc[k];
    __syncthreads();

    float ssum = 0.f;
    #pragma unroll
    for (int ww = 0; ww < 8; ++ww) ssum += red[ww][threadIdx.x];
    g_part[chunk][b][tile * 256 + threadIdx.x] = ssum;
}

// Column pass stage 2: b_j = 1 / sum_chunks partial.
// grid (BATCH*N/256), 256 threads.
__global__ void k_col_combine() {
    const int idx = blockIdx.x * 256 + threadIdx.x;  // b*N + j
    const int b = idx >> 10;
    const int j = idx & (N - 1);
    float s = 0.f;
    #pragma unroll
    for (int c = 0; c < NCHUNK; ++c) s += g_part[c][b][j];
    g_b[idx] = 1.0f / s;
}

// ---------------------------------------------------------------------------
// Final: out = exp(s) * a_i * b_j. Warp per row, 8 rows per block.
__global__ void k_final(const float* __restrict__ s, float* __restrict__ out) {
    const int w    = threadIdx.x >> 5;
    const int lane = threadIdx.x & 31;
    const int row  = blockIdx.x * 8 + w;
    const int b    = blockIdx.y;
    const size_t base = ((size_t)b * N + row) * N;

    const float a = g_a[b * N + row];
    const float4* __restrict__ bp = reinterpret_cast<const float4*>(&g_b[b * N]);

    #pragma unroll
    for (int k = 0; k < 8; ++k) {
        const int j = (lane + 32 * k) * 4;
        float4 sv = *reinterpret_cast<const float4*>(s + base + j);
        float4 bv = bp[j >> 2];
        float4 o;
        o.x = __expf(sv.x) * (a * bv.x);
        o.y = __expf(sv.y) * (a * bv.y);
        o.z = __expf(sv.z) * (a * bv.z);
        o.w = __expf(sv.w) * (a * bv.w);
        *reinterpret_cast<float4*>(out + base + j) = o;
    }
}

// ---------------------------------------------------------------------------
extern "C" void kernel_launch(void* const* d_in, const int* in_sizes, int n_in,
                              void* d_out, int out_size) {
    const float* s = (const float*)d_in[0];
    float* out = (float*)d_out;

    dim3 rows_grid(N / 8, BATCH);          // (128, 32)
    dim3 colp_grid(4, NCHUNK, BATCH);      // (4, 8, 32) = 1024 blocks

    k_exp_rowsum<<<rows_grid, 256>>>(s);   // iter 0 (row) fused

    for (int it = 1; it <= 9; ++it) {
        if (it & 1) {
            k_col_partial<<<colp_grid, 256>>>();
            k_col_combine<<<(BATCH * N) / 256, 256>>>();
        } else {
            k_row<<<rows_grid, 256>>>();
        }
    }

    k_final<<<rows_grid, 256>>>(s, out);
}

// round 4
// speedup vs baseline: 1.0768x; 1.0768x over previous
#include <cuda_runtime.h>
#include <cuda_bf16.h>
#include <cstdint>

// Sinkhorn, 32 x 1024 x 1024, tau=1, 10 iterations — single persistent kernel.
// Linear-domain rank-1 scaling:
//   E = exp(s); even iter: a_i = 1/sum_j E_ij b_j ; odd iter: b_j = 1/sum_i E_ij a_i
//   out = exp(s) * a_i * b_j   (fp32 exp recomputed at the end)
// Each batch (2 MB E in bf16) is owned by 4 co-resident blocks that sync via a
// per-batch atomic barrier, so all 9 GEMV passes hit L2, not DRAM.

#define BATCH 32
#define N 1024
#define BPB 4                  // blocks per batch (grid = 4 x 32 = 128 blocks, all resident)
#define TPB 512
#define WPB 16                 // warps per block
#define RPB 256                // rows per block (N / BPB)
#define CPB 256                // cols per block (N / BPB)

__device__ __nv_bfloat16 g_E[(size_t)BATCH * N * N];   // 64 MB scratch
__device__ float g_a[BATCH * N];
__device__ float g_b[BATCH * N];
__device__ unsigned g_bar[BATCH * 32];                 // one counter per batch, 128B-padded

__global__ void k_zero_bar() {
    g_bar[threadIdx.x * 32] = 0u;
}

__global__ void __launch_bounds__(TPB, 1) k_sinkhorn(const float* __restrict__ s,
                                                     float* __restrict__ out) {
    const int part = blockIdx.x;          // 0..3
    const int b    = blockIdx.y;          // 0..31
    const int w    = threadIdx.x >> 5;    // 0..15
    const int lane = threadIdx.x & 31;
    const size_t bN2 = (size_t)b * N * N;

    __shared__ float sh[N];               // a or b staging (4 KB)
    __shared__ float red[WPB][CPB];       // col-pass reduction (16 KB)

    unsigned bar_target = 0;
    unsigned* const barp = &g_bar[b * 32];

    // ---- per-batch barrier: release-fence, arrive, spin, acquire-fence ----
    auto batch_barrier = [&]() {
        __threadfence();
        __syncthreads();
        bar_target += BPB;
        if (threadIdx.x == 0) {
            atomicAdd(barp, 1u);
            while (*(volatile unsigned*)barp < bar_target) { }
            __threadfence();
        }
        __syncthreads();
    };

    // ================= phase 0: E = exp(s), a = 1/rowsum =================
    #pragma unroll 1
    for (int rr = 0; rr < 16; ++rr) {
        const int row = part * RPB + rr * WPB + w;
        const size_t base = bN2 + (size_t)row * N;
        float sum = 0.f;
        #pragma unroll
        for (int k = 0; k < 8; ++k) {
            const int j = (lane + 32 * k) * 4;
            float4 sv = *reinterpret_cast<const float4*>(s + base + j);
            float e0 = __expf(sv.x), e1 = __expf(sv.y);
            float e2 = __expf(sv.z), e3 = __expf(sv.w);
            __nv_bfloat162 p0 = __floats2bfloat162_rn(e0, e1);
            __nv_bfloat162 p1 = __floats2bfloat162_rn(e2, e3);
            uint2 packed;
            packed.x = *reinterpret_cast<uint32_t*>(&p0);
            packed.y = *reinterpret_cast<uint32_t*>(&p1);
            *reinterpret_cast<uint2*>(&g_E[base + j]) = packed;
            sum += (e0 + e1) + (e2 + e3);
        }
        #pragma unroll
        for (int o = 16; o > 0; o >>= 1) sum += __shfl_down_sync(0xFFFFFFFFu, sum, o);
        if (lane == 0) g_a[b * N + row] = 1.0f / sum;
    }
    batch_barrier();

    // ================= iterations 1..9 =================
    #pragma unroll 1
    for (int it = 1; it <= 9; ++it) {
        if (it & 1) {
            // ---- column pass: b_j = 1 / sum_i E_ij a_i (block owns 256 cols) ----
            for (int t = threadIdx.x; t < N / 4; t += TPB)
                reinterpret_cast<float4*>(sh)[t] =
                    __ldcg(&reinterpret_cast<const float4*>(&g_a[b * N])[t]);
            __syncthreads();

            const int col = part * CPB + lane * 8;
            const size_t cb = bN2 + col;
            float acc[8] = {0.f, 0.f, 0.f, 0.f, 0.f, 0.f, 0.f, 0.f};
            #pragma unroll 1
            for (int it4 = 0; it4 < 16; ++it4) {
                uint4 u[4];
                float av[4];
                #pragma unroll
                for (int v = 0; v < 4; ++v) {
                    const int r = (it4 * 4 + v) * WPB + w;
                    u[v]  = *reinterpret_cast<const uint4*>(&g_E[cb + (size_t)r * N]);
                    av[v] = sh[r];
                }
                #pragma unroll
                for (int v = 0; v < 4; ++v) {
                    float2 f0 = __bfloat1622float2(*reinterpret_cast<__nv_bfloat162*>(&u[v].x));
                    float2 f1 = __bfloat1622float2(*reinterpret_cast<__nv_bfloat162*>(&u[v].y));
                    float2 f2 = __bfloat1622float2(*reinterpret_cast<__nv_bfloat162*>(&u[v].z));
                    float2 f3 = __bfloat1622float2(*reinterpret_cast<__nv_bfloat162*>(&u[v].w));
                    acc[0] = fmaf(av[v], f0.x, acc[0]);
                    acc[1] = fmaf(av[v], f0.y, acc[1]);
                    acc[2] = fmaf(av[v], f1.x, acc[2]);
                    acc[3] = fmaf(av[v], f1.y, acc[3]);
                    acc[4] = fmaf(av[v], f2.x, acc[4]);
                    acc[5] = fmaf(av[v], f2.y, acc[5]);
                    acc[6] = fmaf(av[v], f3.x, acc[6]);
                    acc[7] = fmaf(av[v], f3.y, acc[7]);
                }
            }
            #pragma unroll
            for (int k = 0; k < 8; ++k) red[w][lane * 8 + k] = acc[k];
            __syncthreads();
            if (threadIdx.x < CPB) {
                float ssum = 0.f;
                #pragma unroll
                for (int ww = 0; ww < WPB; ++ww) ssum += red[ww][threadIdx.x];
                g_b[b * N + part * CPB + threadIdx.x] = 1.0f / ssum;
            }
        } else {
            // ---- row pass: a_i = 1 / sum_j E_ij b_j (warp per row, 16 rows/warp) ----
            for (int t = threadIdx.x; t < N / 4; t += TPB)
                reinterpret_cast<float4*>(sh)[t] =
                    __ldcg(&reinterpret_cast<const float4*>(&g_b[b * N])[t]);
            __syncthreads();

            #pragma unroll 1
            for (int rr = 0; rr < 16; ++rr) {
                const int row = part * RPB + rr * WPB + w;
                const size_t base = bN2 + (size_t)row * N;
                float sum = 0.f;
                #pragma unroll
                for (int k = 0; k < 4; ++k) {
                    const int j = lane * 8 + 256 * k;
                    uint4 u = *reinterpret_cast<const uint4*>(&g_E[base + j]);
                    float4 bv0 = *reinterpret_cast<const float4*>(sh + j);
                    float4 bv1 = *reinterpret_cast<const float4*>(sh + j + 4);
                    float2 f0 = __bfloat1622float2(*reinterpret_cast<__nv_bfloat162*>(&u.x));
                    float2 f1 = __bfloat1622float2(*reinterpret_cast<__nv_bfloat162*>(&u.y));
                    float2 f2 = __bfloat1622float2(*reinterpret_cast<__nv_bfloat162*>(&u.z));
                    float2 f3 = __bfloat1622float2(*reinterpret_cast<__nv_bfloat162*>(&u.w));
                    sum = fmaf(f0.x, bv0.x, sum); sum = fmaf(f0.y, bv0.y, sum);
                    sum = fmaf(f1.x, bv0.z, sum); sum = fmaf(f1.y, bv0.w, sum);
                    sum = fmaf(f2.x, bv1.x, sum); sum = fmaf(f2.y, bv1.y, sum);
                    sum = fmaf(f3.x, bv1.z, sum); sum = fmaf(f3.y, bv1.w, sum);
                }
                #pragma unroll
                for (int o = 16; o > 0; o >>= 1) sum += __shfl_down_sync(0xFFFFFFFFu, sum, o);
                if (lane == 0) g_a[b * N + row] = 1.0f / sum;
            }
        }
        batch_barrier();
    }

    // ================= final: out = exp(s) * a_i * b_j =================
    for (int t = threadIdx.x; t < N / 4; t += TPB)
        reinterpret_cast<float4*>(sh)[t] =
            __ldcg(&reinterpret_cast<const float4*>(&g_b[b * N])[t]);
    __syncthreads();

    #pragma unroll 1
    for (int rr = 0; rr < 16; ++rr) {
        const int row = part * RPB + rr * WPB + w;
        const size_t base = bN2 + (size_t)row * N;
        const float a = __ldcg(&g_a[b * N + row]);
        #pragma unroll
        for (int k = 0; k < 8; ++k) {
            const int j = (lane + 32 * k) * 4;
            float4 sv = *reinterpret_cast<const float4*>(s + base + j);
            float4 o;
            o.x = __expf(sv.x) * (a * sh[j]);
            o.y = __expf(sv.y) * (a * sh[j + 1]);
            o.z = __expf(sv.z) * (a * sh[j + 2]);
            o.w = __expf(sv.w) * (a * sh[j + 3]);
            *reinterpret_cast<float4*>(out + base + j) = o;
        }
    }
}

// ---------------------------------------------------------------------------
extern "C" void kernel_launch(void* const* d_in, const int* in_sizes, int n_in,
                              void* d_out, int out_size) {
    const float* s = (const float*)d_in[0];
    float* out = (float*)d_out;

    k_zero_bar<<<1, BATCH>>>();
    k_sinkhorn<<<dim3(BPB, BATCH), TPB>>>(s, out);
}

// round 5
// speedup vs baseline: 1.1744x; 1.0906x over previous
#include <cuda_runtime.h>
#include <cuda_bf16.h>
#include <cstdint>

// Sinkhorn, 32 x 1024 x 1024, tau=1, 10 iterations — single persistent kernel.
//   E = exp(s); even iter: a_i = 1/sum_j E_ij b_j ; odd iter: b_j = 1/sum_i E_ij a_i
//   out = exp(s) * a_i * b_j   (fp32 exp recomputed at the end)
// 8 co-resident blocks per batch sync via a per-batch atomic barrier, so the 9
// GEMV passes read E (2 MB/batch, bf16) from L2. 2 blocks/SM for occupancy.

#define BATCH 32
#define N 1024
#define BPB 8                  // blocks per batch (grid = 8 x 32 = 256 blocks)
#define TPB 512
#define WPB 16                 // warps per block
#define RPB 128                // rows per block (N / BPB)
#define CPB 128                // cols per block (N / BPB)

__device__ __nv_bfloat16 g_E[(size_t)BATCH * N * N];   // 64 MB scratch
__device__ float g_a[BATCH * N];
__device__ float g_b[BATCH * N];
__device__ unsigned g_bar[BATCH * 32];                 // per-batch counter, 128B-padded

__global__ void k_zero_bar() {
    g_bar[threadIdx.x * 32] = 0u;
}

__global__ void __launch_bounds__(TPB, 2) k_sinkhorn(const float* __restrict__ s,
                                                     float* __restrict__ out) {
    const int part = blockIdx.x;          // 0..7
    const int b    = blockIdx.y;          // 0..31
    const int w    = threadIdx.x >> 5;    // 0..15
    const int lane = threadIdx.x & 31;
    const size_t bN2 = (size_t)b * N * N;

    __shared__ float sh[N];               // a or b staging (4 KB)
    __shared__ float red[WPB][CPB];       // col-pass reduction (8 KB)

    unsigned bar_target = 0;
    unsigned* const barp = &g_bar[b * 32];

    auto batch_barrier = [&]() {
        __threadfence();
        __syncthreads();
        bar_target += BPB;
        if (threadIdx.x == 0) {
            atomicAdd(barp, 1u);
            while (*(volatile unsigned*)barp < bar_target) { }
            __threadfence();
        }
        __syncthreads();
    };

    // ================= phase 0: E = exp(s), a = 1/rowsum =================
    #pragma unroll 1
    for (int rr = 0; rr < RPB / WPB; ++rr) {
        const int row = part * RPB + rr * WPB + w;
        const size_t base = bN2 + (size_t)row * N;
        float sum = 0.f;
        #pragma unroll
        for (int k = 0; k < 8; ++k) {
            const int j = (lane + 32 * k) * 4;
            float4 sv = *reinterpret_cast<const float4*>(s + base + j);
            float e0 = __expf(sv.x), e1 = __expf(sv.y);
            float e2 = __expf(sv.z), e3 = __expf(sv.w);
            __nv_bfloat162 p0 = __floats2bfloat162_rn(e0, e1);
            __nv_bfloat162 p1 = __floats2bfloat162_rn(e2, e3);
            uint2 packed;
            packed.x = *reinterpret_cast<uint32_t*>(&p0);
            packed.y = *reinterpret_cast<uint32_t*>(&p1);
            *reinterpret_cast<uint2*>(&g_E[base + j]) = packed;
            sum += (e0 + e1) + (e2 + e3);
        }
        #pragma unroll
        for (int o = 16; o > 0; o >>= 1) sum += __shfl_down_sync(0xFFFFFFFFu, sum, o);
        if (lane == 0) g_a[b * N + row] = 1.0f / sum;
    }
    batch_barrier();

    // ================= iterations 1..9 =================
    #pragma unroll 1
    for (int it = 1; it <= 9; ++it) {
        if (it & 1) {
            // ---- column pass: b_j = 1/sum_i E_ij a_i. Block owns 128 cols.
            // Warp: 2 rows (lane>>4) x 128 cols ((lane&15)*8, uint4 loads).
            for (int t = threadIdx.x; t < N / 4; t += TPB)
                reinterpret_cast<float4*>(sh)[t] =
                    __ldcg(&reinterpret_cast<const float4*>(&g_a[b * N])[t]);
            __syncthreads();

            const int col = part * CPB + (lane & 15) * 8;
            const int rofs = w * 2 + (lane >> 4);
            const size_t cb = bN2 + col;
            float acc[8] = {0.f, 0.f, 0.f, 0.f, 0.f, 0.f, 0.f, 0.f};
            #pragma unroll 1
            for (int it4 = 0; it4 < 8; ++it4) {
                uint4 u[4];
                float av[4];
                #pragma unroll
                for (int v = 0; v < 4; ++v) {
                    const int r = (it4 * 4 + v) * 32 + rofs;
                    u[v]  = *reinterpret_cast<const uint4*>(&g_E[cb + (size_t)r * N]);
                    av[v] = sh[r];
                }
                #pragma unroll
                for (int v = 0; v < 4; ++v) {
                    float2 f0 = __bfloat1622float2(*reinterpret_cast<__nv_bfloat162*>(&u[v].x));
                    float2 f1 = __bfloat1622float2(*reinterpret_cast<__nv_bfloat162*>(&u[v].y));
                    float2 f2 = __bfloat1622float2(*reinterpret_cast<__nv_bfloat162*>(&u[v].z));
                    float2 f3 = __bfloat1622float2(*reinterpret_cast<__nv_bfloat162*>(&u[v].w));
                    acc[0] = fmaf(av[v], f0.x, acc[0]);
                    acc[1] = fmaf(av[v], f0.y, acc[1]);
                    acc[2] = fmaf(av[v], f1.x, acc[2]);
                    acc[3] = fmaf(av[v], f1.y, acc[3]);
                    acc[4] = fmaf(av[v], f2.x, acc[4]);
                    acc[5] = fmaf(av[v], f2.y, acc[5]);
                    acc[6] = fmaf(av[v], f3.x, acc[6]);
                    acc[7] = fmaf(av[v], f3.y, acc[7]);
                }
            }
            // fold the two row-halves of the warp, then cross-warp in shared
            #pragma unroll
            for (int k = 0; k < 8; ++k)
                acc[k] += __shfl_xor_sync(0xFFFFFFFFu, acc[k], 16);
            if (lane < 16) {
                #pragma unroll
                for (int k = 0; k < 8; ++k) red[w][lane * 8 + k] = acc[k];
            }
            __syncthreads();
            if (threadIdx.x < CPB) {
                float ssum = 0.f;
                #pragma unroll
                for (int ww = 0; ww < WPB; ++ww) ssum += red[ww][threadIdx.x];
                g_b[b * N + part * CPB + threadIdx.x] = 1.0f / ssum;
            }
        } else {
            // ---- row pass: a_i = 1/sum_j E_ij b_j. Warp per row, 8 rows/warp.
            for (int t = threadIdx.x; t < N / 4; t += TPB)
                reinterpret_cast<float4*>(sh)[t] =
                    __ldcg(&reinterpret_cast<const float4*>(&g_b[b * N])[t]);
            __syncthreads();

            #pragma unroll 1
            for (int rr = 0; rr < RPB / WPB; ++rr) {
                const int row = part * RPB + rr * WPB + w;
                const size_t base = bN2 + (size_t)row * N;
                float sum = 0.f;
                #pragma unroll
                for (int k = 0; k < 4; ++k) {
                    const int j = lane * 8 + 256 * k;
                    uint4 u = *reinterpret_cast<const uint4*>(&g_E[base + j]);
                    float4 bv0 = *reinterpret_cast<const float4*>(sh + j);
                    float4 bv1 = *reinterpret_cast<const float4*>(sh + j + 4);
                    float2 f0 = __bfloat1622float2(*reinterpret_cast<__nv_bfloat162*>(&u.x));
                    float2 f1 = __bfloat1622float2(*reinterpret_cast<__nv_bfloat162*>(&u.y));
                    float2 f2 = __bfloat1622float2(*reinterpret_cast<__nv_bfloat162*>(&u.z));
                    float2 f3 = __bfloat1622float2(*reinterpret_cast<__nv_bfloat162*>(&u.w));
                    sum = fmaf(f0.x, bv0.x, sum); sum = fmaf(f0.y, bv0.y, sum);
                    sum = fmaf(f1.x, bv0.z, sum); sum = fmaf(f1.y, bv0.w, sum);
                    sum = fmaf(f2.x, bv1.x, sum); sum = fmaf(f2.y, bv1.y, sum);
                    sum = fmaf(f3.x, bv1.z, sum); sum = fmaf(f3.y, bv1.w, sum);
                }
                #pragma unroll
                for (int o = 16; o > 0; o >>= 1) sum += __shfl_down_sync(0xFFFFFFFFu, sum, o);
                if (lane == 0) g_a[b * N + row] = 1.0f / sum;
            }
        }
        batch_barrier();
    }

    // ================= final: out = exp(s) * a_i * b_j =================
    for (int t = threadIdx.x; t < N / 4; t += TPB)
        reinterpret_cast<float4*>(sh)[t] =
            __ldcg(&reinterpret_cast<const float4*>(&g_b[b * N])[t]);
    __syncthreads();

    #pragma unroll 1
    for (int rr = 0; rr < RPB / WPB; ++rr) {
        const int row = part * RPB + rr * WPB + w;
        const size_t base = bN2 + (size_t)row * N;
        const float a = __ldcg(&g_a[b * N + row]);
        #pragma unroll
        for (int k = 0; k < 8; ++k) {
            const int j = (lane + 32 * k) * 4;
            float4 sv = *reinterpret_cast<const float4*>(s + base + j);
            float4 o;
            o.x = __expf(sv.x) * (a * sh[j]);
            o.y = __expf(sv.y) * (a * sh[j + 1]);
            o.z = __expf(sv.z) * (a * sh[j + 2]);
            o.w = __expf(sv.w) * (a * sh[j + 3]);
            *reinterpret_cast<float4*>(out + base + j) = o;
        }
    }
}

// ---------------------------------------------------------------------------
extern "C" void kernel_launch(void* const* d_in, const int* in_sizes, int n_in,
                              void* d_out, int out_size) {
    const float* s = (const float*)d_in[0];
    float* out = (float*)d_out;

    k_zero_bar<<<1, BATCH>>>();
    k_sinkhorn<<<dim3(BPB, BATCH), TPB>>>(s, out);
}